// round 1
// baseline (speedup 1.0000x reference)
#include <cuda_runtime.h>
#include <math.h>

// Shapes are fixed by the problem: B=512, L=256, L1=256, D=128.
#define B_   512
#define L_   256
#define D_   128
#define L1_  256
#define RS   129          // padded smem row stride (conflict-free: 129 % 32 == 1)
#define EPSF 0.01f

// Scratch for h_last [B, D] (no allocations allowed -> device global)
__device__ float g_hlast[B_ * D_];

// ---------------------------------------------------------------------------
// Kernel A: per-batch self cosine-attention, restricted to rows where
// last*mask != 0, accumulating h_last[b] = sum_i (h_self_i + h_i).
// One CTA per batch, 256 threads, hist_1[b] resident in SMEM.
// ---------------------------------------------------------------------------
__global__ __launch_bounds__(256, 1)
void self_attn_kernel(const int* __restrict__ seq,
                      const int* __restrict__ last,
                      const float* __restrict__ h1)
{
    extern __shared__ float sm[];
    float* Hs   = sm;                      // [256][129]
    float* inv  = Hs + L_ * RS;            // [256] rsqrt(||h_i||^2 + eps)
    float* msk  = inv + L_;                // [256] key mask
    float* wrow = msk + L_;                // [8 warps][4 rows][256] w values
    float* hlp  = wrow + 8 * 4 * L_;       // [8 warps][128] per-warp h_last partials
    int*   sel  = (int*)(hlp + 8 * D_);    // [256] selected row indices
    __shared__ int nsel_s;

    const int b    = blockIdx.x;
    const int tid  = threadIdx.x;
    const int wid  = tid >> 5;
    const int lane = tid & 31;

    // ---- load hist_1[b] into padded SMEM (float4 gmem reads) ----
    const float* src = h1 + (size_t)b * L_ * D_;
    for (int idx = tid; idx < L_ * D_ / 4; idx += 256) {
        float4 v = ((const float4*)src)[idx];
        int i = idx >> 5;            // idx / (D/4)
        int d = (idx & 31) << 2;
        float* p = Hs + i * RS + d;
        p[0] = v.x; p[1] = v.y; p[2] = v.z; p[3] = v.w;
    }
    for (int idx = tid; idx < 8 * D_; idx += 256) hlp[idx] = 0.f;
    __syncthreads();

    // ---- norms, mask, selection ----
    if (tid < L_) {
        const float* r = Hs + tid * RS;
        float s = 0.f;
        #pragma unroll 8
        for (int d = 0; d < D_; ++d) s += r[d] * r[d];
        inv[tid] = rsqrtf(s + EPSF);
        msk[tid] = (seq[b * L_ + tid] != 0) ? 1.f : 0.f;
    }
    if (tid == 0) {   // deterministic, ordered selection list
        int n = 0;
        for (int i = 0; i < L_; ++i)
            if (last[b * L_ + i] != 0 && seq[b * L_ + i] != 0) sel[n++] = i;
        nsel_s = n;
    }
    __syncthreads();
    const int nsel = nsel_s;

    float* myw  = wrow + wid * 4 * L_;
    float* myhl = hlp + wid * D_;

    // ---- main loop: 4 query rows per warp per iteration ----
    for (int base = wid * 4; base < nsel; base += 32) {
        const int nr = nsel - base;   // >= 1
        const int i0 = sel[base];
        const int i1 = sel[base + ((nr > 1) ? 1 : 0)];
        const int i2 = sel[base + ((nr > 2) ? 2 : 0)];
        const int i3 = sel[base + ((nr > 3) ? 3 : 0)];

        // --- S phase: dots for 4 rows x 8 key-columns per lane ---
        float acc[4][8];
        #pragma unroll
        for (int r = 0; r < 4; ++r)
            #pragma unroll
            for (int c = 0; c < 8; ++c) acc[r][c] = 0.f;

        const float* R0 = Hs + i0 * RS;
        const float* R1 = Hs + i1 * RS;
        const float* R2 = Hs + i2 * RS;
        const float* R3 = Hs + i3 * RS;
        const float* Kp = Hs + lane * RS;

        #pragma unroll 4
        for (int d = 0; d < D_; ++d) {
            const float q0 = R0[d], q1 = R1[d], q2 = R2[d], q3 = R3[d];
            #pragma unroll
            for (int c = 0; c < 8; ++c) {
                const float kv = Kp[c * 32 * RS + d];
                acc[0][c] += q0 * kv;
                acc[1][c] += q1 * kv;
                acc[2][c] += q2 * kv;
                acc[3][c] += q3 * kv;
            }
        }

        // --- w = exp(cos)*mask, row sums ---
        const float iq0 = inv[i0], iq1 = inv[i1], iq2 = inv[i2], iq3 = inv[i3];
        float ws0 = 0.f, ws1 = 0.f, ws2 = 0.f, ws3 = 0.f;
        #pragma unroll
        for (int c = 0; c < 8; ++c) {
            const int j = lane + 32 * c;
            const float ivj = inv[j];
            const float mj  = msk[j];
            float w;
            w = __expf(acc[0][c] * iq0 * ivj) * mj; ws0 += w; myw[0 * L_ + j] = w;
            w = __expf(acc[1][c] * iq1 * ivj) * mj; ws1 += w; myw[1 * L_ + j] = w;
            w = __expf(acc[2][c] * iq2 * ivj) * mj; ws2 += w; myw[2 * L_ + j] = w;
            w = __expf(acc[3][c] * iq3 * ivj) * mj; ws3 += w; myw[3 * L_ + j] = w;
        }
        #pragma unroll
        for (int off = 16; off; off >>= 1) {
            ws0 += __shfl_xor_sync(0xffffffffu, ws0, off);
            ws1 += __shfl_xor_sync(0xffffffffu, ws1, off);
            ws2 += __shfl_xor_sync(0xffffffffu, ws2, off);
            ws3 += __shfl_xor_sync(0xffffffffu, ws3, off);
        }
        __syncwarp();   // myw writes visible before cross-lane reads

        // --- O phase: acc_d = sum_j w_j * H[j][d]; lane covers 4 d's ---
        float oacc[4][4];
        #pragma unroll
        for (int r = 0; r < 4; ++r)
            #pragma unroll
            for (int c = 0; c < 4; ++c) oacc[r][c] = 0.f;

        for (int j = 0; j < L_; ++j) {
            const float w0 = myw[0 * L_ + j];
            const float w1 = myw[1 * L_ + j];
            const float w2 = myw[2 * L_ + j];
            const float w3 = myw[3 * L_ + j];
            const float* Hj = Hs + j * RS + lane;
            #pragma unroll
            for (int c = 0; c < 4; ++c) {
                const float hv = Hj[c * 32];
                oacc[0][c] += w0 * hv;
                oacc[1][c] += w1 * hv;
                oacc[2][c] += w2 * hv;
                oacc[3][c] += w3 * hv;
            }
        }

        // --- accumulate (h_self + h) into this warp's h_last partial ---
        const int   ii[4] = { i0, i1, i2, i3 };
        const float ws[4] = { ws0, ws1, ws2, ws3 };
        #pragma unroll
        for (int r = 0; r < 4; ++r) {
            if (base + r < nsel) {
                const float invw = 1.f / ws[r];
                const float* Hi = Hs + ii[r] * RS + lane;
                #pragma unroll
                for (int c = 0; c < 4; ++c) {
                    const int d = lane + 32 * c;
                    myhl[d] += oacc[r][c] * invw + Hi[c * 32];
                }
            }
        }
        __syncwarp();   // protect myw against next iteration's writes
    }

    __syncthreads();
    if (tid < D_) {   // deterministic fixed-order reduction over warps
        float s = 0.f;
        #pragma unroll
        for (int w = 0; w < 8; ++w) s += hlp[w * D_ + tid];
        g_hlast[b * D_ + tid] = s;
    }
}

// ---------------------------------------------------------------------------
// Kernel B: cross cosine-attention of h_last over hist_2, then relu(h @ W).
// One CTA per batch, 256 threads. Memory-bound, tiny.
// ---------------------------------------------------------------------------
__global__ __launch_bounds__(256, 4)
void cross_kernel(const int* __restrict__ seq1,
                  const float* __restrict__ h2,
                  const float* __restrict__ W,
                  float* __restrict__ out)
{
    __shared__ float hl[D_];
    __shared__ float w2s[L1_];
    __shared__ float wsump[8];
    __shared__ float haccp[8][D_];
    __shared__ float hv[D_];
    __shared__ float invq_s;

    const int b    = blockIdx.x;
    const int tid  = threadIdx.x;
    const int wid  = tid >> 5;
    const int lane = tid & 31;

    if (tid < D_) hl[tid] = g_hlast[b * D_ + tid];
    __syncthreads();

    if (tid < 32) {   // ||h_last||^2 via one warp
        float s = 0.f;
        #pragma unroll
        for (int c = 0; c < 4; ++c) { float v = hl[tid + 32 * c]; s += v * v; }
        #pragma unroll
        for (int off = 16; off; off >>= 1) s += __shfl_xor_sync(0xffffffffu, s, off);
        if (tid == 0) invq_s = rsqrtf(s + EPSF);
    }
    __syncthreads();
    const float invq = invq_s;
    const float* H2 = h2 + (size_t)b * L1_ * D_;

    // pass 1: w2[k] and per-warp wsum (fixed order -> deterministic)
    float wpart = 0.f;
    for (int k = wid; k < L1_; k += 8) {
        float4 v = ((const float4*)(H2 + k * D_))[lane];
        float dot = v.x * hl[lane * 4]     + v.y * hl[lane * 4 + 1]
                  + v.z * hl[lane * 4 + 2] + v.w * hl[lane * 4 + 3];
        float nk  = v.x * v.x + v.y * v.y + v.z * v.z + v.w * v.w;
        #pragma unroll
        for (int off = 16; off; off >>= 1) {
            dot += __shfl_xor_sync(0xffffffffu, dot, off);
            nk  += __shfl_xor_sync(0xffffffffu, nk,  off);
        }
        float w = __expf(dot * rsqrtf(nk + EPSF) * invq)
                * ((seq1[b * L1_ + k] != 0) ? 1.f : 0.f);
        if (lane == 0) w2s[k] = w;
        wpart += w;   // identical on all lanes after full reduction
    }
    if (lane == 0) wsump[wid] = wpart;
    __syncthreads();

    // pass 2: weighted sum of hist_2 rows (per-warp partials)
    float a0 = 0.f, a1 = 0.f, a2 = 0.f, a3 = 0.f;
    for (int k = wid; k < L1_; k += 8) {
        const float w = w2s[k];
        float4 v = ((const float4*)(H2 + k * D_))[lane];
        a0 += w * v.x; a1 += w * v.y; a2 += w * v.z; a3 += w * v.w;
    }
    haccp[wid][lane * 4]     = a0;
    haccp[wid][lane * 4 + 1] = a1;
    haccp[wid][lane * 4 + 2] = a2;
    haccp[wid][lane * 4 + 3] = a3;
    __syncthreads();

    if (tid < D_) {
        float wsum = 0.f;
        #pragma unroll
        for (int w = 0; w < 8; ++w) wsum += wsump[w];
        float s = 0.f;
        #pragma unroll
        for (int w = 0; w < 8; ++w) s += haccp[w][tid];
        hv[tid] = s / wsum;
    }
    __syncthreads();

    // out = relu(hv @ W); thread t -> output column t
    if (tid < D_) {
        float o = 0.f;
        #pragma unroll 8
        for (int d = 0; d < D_; ++d) o += hv[d] * W[d * D_ + tid];
        out[b * D_ + tid] = fmaxf(o, 0.f);
    }
}

// ---------------------------------------------------------------------------
extern "C" void kernel_launch(void* const* d_in, const int* in_sizes, int n_in,
                              void* d_out, int out_size)
{
    const int*   seq  = (const int*)d_in[0];    // sequence       [B, L]
    const int*   last = (const int*)d_in[1];    // last_sequence  [B, L]
    const int*   seq1 = (const int*)d_in[2];    // sequence_1     [B, L1]
    const float* h1   = (const float*)d_in[3];  // hist_1         [B, L, D]
    const float* h2   = (const float*)d_in[4];  // hist_2         [B, L1, D]
    const float* W    = (const float*)d_in[5];  // W              [D, D]
    float* out = (float*)d_out;                 // [B, 1, D] fp32

    const size_t smemA = (size_t)(L_ * RS + L_ + L_ + 8 * 4 * L_ + 8 * D_) * sizeof(float)
                       + (size_t)L_ * sizeof(int);
    cudaFuncSetAttribute(self_attn_kernel,
                         cudaFuncAttributeMaxDynamicSharedMemorySize, (int)smemA);

    self_attn_kernel<<<B_, 256, smemA>>>(seq, last, h1);
    cross_kernel<<<B_, 256>>>(seq1, h2, W, out);
}